// round 1
// baseline (speedup 1.0000x reference)
#include <cuda_runtime.h>
#include <math.h>

#define NN 100000
#define EE 1600000
#define HD 128
#define CD 40

// -------- scratch (static __device__ arrays; allocation forbidden) --------
__device__ float g_bufA[(size_t)NN * HD];   // 51.2 MB
__device__ float g_bufB[(size_t)NN * HD];   // 51.2 MB
__device__ int   g_deg_out[NN];
__device__ int   g_deg_in[NN];
__device__ float g_norm_out[NN];
__device__ float g_norm_in[NN];
__device__ int   g_offs[NN + 1];
__device__ int   g_cursor[NN];
__device__ int   g_bsums[128];
__device__ int   g_csr[EE];                 // 6.4 MB

// ---------------------------------------------------------------------------
// Degrees + norms + CSR build
// ---------------------------------------------------------------------------
__global__ void k_zero() {
    int i = blockIdx.x * blockDim.x + threadIdx.x;
    if (i < NN) { g_deg_out[i] = 0; g_deg_in[i] = 0; g_cursor[i] = 0; }
}

__global__ void k_deg(const int* __restrict__ src, const int* __restrict__ dst) {
    int e = blockIdx.x * blockDim.x + threadIdx.x;
    if (e < EE) {
        atomicAdd(&g_deg_out[src[e]], 1);
        atomicAdd(&g_deg_in[dst[e]], 1);
    }
}

__global__ void k_norm() {
    int i = blockIdx.x * blockDim.x + threadIdx.x;
    if (i < NN) {
        int d0 = g_deg_out[i];
        int d1 = g_deg_in[i];
        g_norm_out[i] = d0 > 0 ? rsqrtf((float)d0) : 0.f;
        g_norm_in[i]  = d1 > 0 ? rsqrtf((float)d1) : 0.f;
    }
}

__global__ void k_scan1() {
    __shared__ int sh[1024];
    int i = blockIdx.x * 1024 + threadIdx.x;
    int v = (i < NN) ? g_deg_in[i] : 0;
    sh[threadIdx.x] = v;
    __syncthreads();
    #pragma unroll
    for (int d = 1; d < 1024; d <<= 1) {
        int t = 0;
        if ((int)threadIdx.x >= d) t = sh[threadIdx.x - d];
        __syncthreads();
        sh[threadIdx.x] += t;
        __syncthreads();
    }
    if (i < NN) g_offs[i + 1] = sh[threadIdx.x];
    if (threadIdx.x == 1023) g_bsums[blockIdx.x] = sh[1023];
}

__global__ void k_scan2(int nb) {
    if (threadIdx.x == 0 && blockIdx.x == 0) {
        int run = 0;
        for (int b = 0; b < nb; b++) { int t = g_bsums[b]; g_bsums[b] = run; run += t; }
    }
}

__global__ void k_scan3() {
    int i = blockIdx.x * blockDim.x + threadIdx.x;
    if (i == 0) g_offs[0] = 0;
    if (i < NN) g_offs[i + 1] += g_bsums[i >> 10];
}

__global__ void k_scatter(const int* __restrict__ src, const int* __restrict__ dst) {
    int e = blockIdx.x * blockDim.x + threadIdx.x;
    if (e < EE) {
        int d = dst[e];
        int pos = g_offs[d] + atomicAdd(&g_cursor[d], 1);
        g_csr[pos] = src[e];
    }
}

// ---------------------------------------------------------------------------
// GEMM 128->128:  g_bufA[r,:] = norm_out[r] * (x[r,:] @ W)
// Tile 128x128, BK=32, 256 threads, 8x8 per thread (split-tile mapping).
// sel==0: x = x_ext (feat);  sel==1: x = g_bufB
// ---------------------------------------------------------------------------
__global__ void __launch_bounds__(256, 2)
gemm128(const float* __restrict__ x_ext, const float* __restrict__ W, int sel) {
    __shared__ float Xs[32][132];   // [k][m], padded
    __shared__ float Ws[32][128];   // [k][n]
    const float* __restrict__ xp = sel ? g_bufB : x_ext;

    int tid  = threadIdx.x;
    int row0 = blockIdx.x * 128;
    int tr = tid >> 4;        // 0..15
    int tc = tid & 15;        // 0..15

    float acc[8][8];
    #pragma unroll
    for (int i = 0; i < 8; i++)
        #pragma unroll
        for (int j = 0; j < 8; j++) acc[i][j] = 0.f;

    for (int k0 = 0; k0 < 128; k0 += 32) {
        // load X tile (128 rows x 32 k) transposed into Xs[k][m]
        #pragma unroll
        for (int i = 0; i < 4; i++) {
            int idx = tid + i * 256;
            int r  = idx >> 3;          // 0..127
            int kq = (idx & 7) << 2;    // 0..28
            float4 v = make_float4(0.f, 0.f, 0.f, 0.f);
            int gr = row0 + r;
            if (gr < NN) v = *(const float4*)&xp[(size_t)gr * 128 + k0 + kq];
            Xs[kq + 0][r] = v.x; Xs[kq + 1][r] = v.y;
            Xs[kq + 2][r] = v.z; Xs[kq + 3][r] = v.w;
        }
        // load W tile (32 k x 128 n)
        #pragma unroll
        for (int i = 0; i < 4; i++) {
            int idx = tid + i * 256;
            int kk = idx >> 5;          // 0..31
            int c  = (idx & 31) << 2;   // 0..124
            *(float4*)&Ws[kk][c] = *(const float4*)&W[(size_t)(k0 + kk) * 128 + c];
        }
        __syncthreads();

        #pragma unroll
        for (int k = 0; k < 32; k++) {
            float a[8], b[8];
            *(float4*)&a[0] = *(const float4*)&Xs[k][tr * 4];
            *(float4*)&a[4] = *(const float4*)&Xs[k][tr * 4 + 64];
            *(float4*)&b[0] = *(const float4*)&Ws[k][tc * 4];
            *(float4*)&b[4] = *(const float4*)&Ws[k][tc * 4 + 64];
            #pragma unroll
            for (int i = 0; i < 8; i++)
                #pragma unroll
                for (int j = 0; j < 8; j++)
                    acc[i][j] = fmaf(a[i], b[j], acc[i][j]);
        }
        __syncthreads();
    }

    // epilogue: scale by norm_out[row]
    #pragma unroll
    for (int i = 0; i < 8; i++) {
        int r  = (i < 4) ? (tr * 4 + i) : (tr * 4 + 64 + (i - 4));
        int gr = row0 + r;
        if (gr >= NN) continue;
        float s = g_norm_out[gr];
        float4 o0 = make_float4(acc[i][0] * s, acc[i][1] * s, acc[i][2] * s, acc[i][3] * s);
        float4 o1 = make_float4(acc[i][4] * s, acc[i][5] * s, acc[i][6] * s, acc[i][7] * s);
        *(float4*)&g_bufA[(size_t)gr * 128 + tc * 4]      = o0;
        *(float4*)&g_bufA[(size_t)gr * 128 + tc * 4 + 64] = o1;
    }
}

// ---------------------------------------------------------------------------
// GEMM 128->40 (layer 2):  g_bufA[r,0:40] = norm_out[r] * (g_bufB[r,:] @ W2)
// 32 rows/block, 256 threads, 5 cols per thread.
// ---------------------------------------------------------------------------
__global__ void __launch_bounds__(256, 4)
gemm40(const float* __restrict__ W2) {
    __shared__ float Xs[32][132];
    __shared__ float Ws[128][40];
    int tid  = threadIdx.x;
    int row0 = blockIdx.x * 32;

    for (int i = tid; i < 128 * 40; i += 256) Ws[i / 40][i % 40] = W2[i];
    #pragma unroll
    for (int i = 0; i < 4; i++) {
        int idx = tid + i * 256;
        int r = idx >> 5;            // 0..31
        int c = (idx & 31) << 2;     // 0..124
        int gr = row0 + r;
        float4 v = make_float4(0.f, 0.f, 0.f, 0.f);
        if (gr < NN) v = *(const float4*)&g_bufB[(size_t)gr * 128 + c];
        *(float4*)&Xs[r][c] = v;
    }
    __syncthreads();

    int r  = tid >> 3;         // 0..31
    int c0 = (tid & 7) * 5;    // 0,5,...,35
    float acc[5] = {0.f, 0.f, 0.f, 0.f, 0.f};
    #pragma unroll 8
    for (int k = 0; k < 128; k++) {
        float a = Xs[r][k];
        #pragma unroll
        for (int j = 0; j < 5; j++) acc[j] = fmaf(a, Ws[k][c0 + j], acc[j]);
    }
    int gr = row0 + r;
    if (gr < NN) {
        float s = g_norm_out[gr];
        #pragma unroll
        for (int j = 0; j < 5; j++) g_bufA[(size_t)gr * 40 + c0 + j] = acc[j] * s;
    }
}

// ---------------------------------------------------------------------------
// Aggregation 128-dim: one warp per dst node; CSR gather-accumulate.
// g_bufB[w,:] = relu( (sum_{e in N(w)} g_bufA[src_e,:]) * norm_in[w] + bias )
// ---------------------------------------------------------------------------
template <int RELU>
__global__ void __launch_bounds__(256)
agg128(const float* __restrict__ bias) {
    int w = (blockIdx.x * blockDim.x + threadIdx.x) >> 5;
    if (w >= NN) return;
    int lane = threadIdx.x & 31;
    int beg = g_offs[w], end = g_offs[w + 1];

    float4 acc = make_float4(0.f, 0.f, 0.f, 0.f);
    int e = beg;
    for (; e + 2 <= end; e += 2) {
        int s0 = g_csr[e];
        int s1 = g_csr[e + 1];
        float4 v0 = *(const float4*)&g_bufA[(size_t)s0 * 128 + lane * 4];
        float4 v1 = *(const float4*)&g_bufA[(size_t)s1 * 128 + lane * 4];
        acc.x += v0.x; acc.y += v0.y; acc.z += v0.z; acc.w += v0.w;
        acc.x += v1.x; acc.y += v1.y; acc.z += v1.z; acc.w += v1.w;
    }
    if (e < end) {
        int s0 = g_csr[e];
        float4 v0 = *(const float4*)&g_bufA[(size_t)s0 * 128 + lane * 4];
        acc.x += v0.x; acc.y += v0.y; acc.z += v0.z; acc.w += v0.w;
    }

    float sc = g_norm_in[w];
    float4 b = *(const float4*)&bias[lane * 4];
    float4 o;
    o.x = fmaf(acc.x, sc, b.x);
    o.y = fmaf(acc.y, sc, b.y);
    o.z = fmaf(acc.z, sc, b.z);
    o.w = fmaf(acc.w, sc, b.w);
    if (RELU) {
        o.x = fmaxf(o.x, 0.f); o.y = fmaxf(o.y, 0.f);
        o.z = fmaxf(o.z, 0.f); o.w = fmaxf(o.w, 0.f);
    }
    *(float4*)&g_bufB[(size_t)w * 128 + lane * 4] = o;
}

// ---------------------------------------------------------------------------
// Aggregation 40-dim (final layer, no relu) -> d_out
// ---------------------------------------------------------------------------
__global__ void __launch_bounds__(256)
agg40(const float* __restrict__ bias, float* __restrict__ out) {
    int w = (blockIdx.x * blockDim.x + threadIdx.x) >> 5;
    if (w >= NN) return;
    int lane = threadIdx.x & 31;
    int beg = g_offs[w], end = g_offs[w + 1];

    float acc0 = 0.f, acc1 = 0.f;
    for (int e = beg; e < end; e++) {
        int s = g_csr[e];
        const float* rp = &g_bufA[(size_t)s * 40];
        acc0 += rp[lane];
        if (lane < 8) acc1 += rp[32 + lane];
    }
    float sc = g_norm_in[w];
    out[(size_t)w * 40 + lane] = fmaf(acc0, sc, bias[lane]);
    if (lane < 8)
        out[(size_t)w * 40 + 32 + lane] = fmaf(acc1, sc, bias[32 + lane]);
}

// ---------------------------------------------------------------------------
extern "C" void kernel_launch(void* const* d_in, const int* in_sizes, int n_in,
                              void* d_out, int out_size) {
    const float* feat = (const float*)d_in[0];
    const int*   src  = (const int*)  d_in[1];
    const int*   dst  = (const int*)  d_in[2];
    const float* W0   = (const float*)d_in[3];
    const float* b0   = (const float*)d_in[4];
    const float* W1   = (const float*)d_in[5];
    const float* b1   = (const float*)d_in[6];
    const float* W2   = (const float*)d_in[7];
    const float* b2   = (const float*)d_in[8];
    float* out = (float*)d_out;

    const int NB = (NN + 255) / 256;
    const int EB = (EE + 255) / 256;
    const int SB = (NN + 1023) / 1024;
    const int AGGB = (NN * 32 + 255) / 256;

    // graph preprocessing
    k_zero<<<NB, 256>>>();
    k_deg<<<EB, 256>>>(src, dst);
    k_norm<<<NB, 256>>>();
    k_scan1<<<SB, 1024>>>();
    k_scan2<<<1, 32>>>(SB);
    k_scan3<<<NB, 256>>>();
    k_scatter<<<EB, 256>>>(src, dst);

    // layer 0
    gemm128<<<(NN + 127) / 128, 256>>>(feat, W0, 0);
    agg128<1><<<AGGB, 256>>>(b0);
    // layer 1
    gemm128<<<(NN + 127) / 128, 256>>>(nullptr, W1, 1);
    agg128<1><<<AGGB, 256>>>(b1);
    // layer 2
    gemm40<<<(NN + 31) / 32, 256>>>(W2);
    agg40<<<AGGB, 256>>>(b2, out);
}

// round 3
// speedup vs baseline: 1.2816x; 1.2816x over previous
#include <cuda_runtime.h>
#include <cuda_bf16.h>
#include <math.h>
#include <stdint.h>

#define NN 100000
#define EE 1600000
#define HD 128
#define CD 40

// -------- scratch (static __device__ arrays; allocation forbidden) --------
__device__ float g_bufA[(size_t)NN * HD];   // 51.2 MB
__device__ float g_bufB[(size_t)NN * HD];   // 51.2 MB
__device__ int   g_deg_out[NN];
__device__ int   g_deg_in[NN];
__device__ float g_norm_out[NN];
__device__ float g_norm_in[NN];
__device__ int   g_offs[NN + 1];
__device__ int   g_cursor[NN];
__device__ int   g_bsums[128];
__device__ int   g_csr[EE];                 // 6.4 MB

// Pre-built W operand tiles: [n][k] bf16, padded row stride 136 elems, hi/lo.
// Layout EXACTLY matches the GEMM's smem W region -> verbatim float4 copy.
__device__ __align__(16) unsigned char g_B0h[128 * 136 * 2];
__device__ __align__(16) unsigned char g_B0l[128 * 136 * 2];
__device__ __align__(16) unsigned char g_B1h[128 * 136 * 2];
__device__ __align__(16) unsigned char g_B1l[128 * 136 * 2];
__device__ __align__(16) unsigned char g_B2h[64 * 136 * 2];
__device__ __align__(16) unsigned char g_B2l[64 * 136 * 2];

// ===========================================================================
// MMA / ldmatrix helpers (baseline sm_80 features -- no 'a'-gated PTX)
// ===========================================================================
__device__ __forceinline__ uint32_t smem_to_u32(const void* p) {
    uint32_t a;
    asm("{ .reg .u64 t; cvta.to.shared.u64 t, %1; cvt.u32.u64 %0, t; }"
        : "=r"(a) : "l"(p));
    return a;
}

#define LDSM4(r, addr) \
    asm volatile("ldmatrix.sync.aligned.m8n8.x4.shared.b16 {%0,%1,%2,%3}, [%4];" \
        : "=r"((r)[0]), "=r"((r)[1]), "=r"((r)[2]), "=r"((r)[3]) : "r"(addr))

#define MMA_BF16(d, a, b0, b1) \
    asm volatile("mma.sync.aligned.m16n8k16.row.col.f32.bf16.bf16.f32 " \
        "{%0,%1,%2,%3}, {%4,%5,%6,%7}, {%8,%9}, {%0,%1,%2,%3};" \
        : "+f"((d)[0]), "+f"((d)[1]), "+f"((d)[2]), "+f"((d)[3]) \
        : "r"((a)[0]), "r"((a)[1]), "r"((a)[2]), "r"((a)[3]), "r"(b0), "r"(b1))

// ===========================================================================
// Degrees + norms + CSR build
// ===========================================================================
__global__ void k_zero() {
    int i = blockIdx.x * blockDim.x + threadIdx.x;
    if (i < NN) { g_deg_out[i] = 0; g_deg_in[i] = 0; g_cursor[i] = 0; }
}

__global__ void k_deg(const int* __restrict__ src, const int* __restrict__ dst) {
    int e = blockIdx.x * blockDim.x + threadIdx.x;
    if (e < EE) {
        atomicAdd(&g_deg_out[src[e]], 1);
        atomicAdd(&g_deg_in[dst[e]], 1);
    }
}

__global__ void k_norm() {
    int i = blockIdx.x * blockDim.x + threadIdx.x;
    if (i < NN) {
        int d0 = g_deg_out[i];
        int d1 = g_deg_in[i];
        g_norm_out[i] = d0 > 0 ? rsqrtf((float)d0) : 0.f;
        g_norm_in[i]  = d1 > 0 ? rsqrtf((float)d1) : 0.f;
    }
}

__global__ void k_scan1() {
    __shared__ int sh[1024];
    int i = blockIdx.x * 1024 + threadIdx.x;
    int v = (i < NN) ? g_deg_in[i] : 0;
    sh[threadIdx.x] = v;
    __syncthreads();
    #pragma unroll
    for (int d = 1; d < 1024; d <<= 1) {
        int t = 0;
        if ((int)threadIdx.x >= d) t = sh[threadIdx.x - d];
        __syncthreads();
        sh[threadIdx.x] += t;
        __syncthreads();
    }
    if (i < NN) g_offs[i + 1] = sh[threadIdx.x];
    if (threadIdx.x == 1023) g_bsums[blockIdx.x] = sh[1023];
}

__global__ void k_scan2(int nb) {
    if (threadIdx.x == 0 && blockIdx.x == 0) {
        int run = 0;
        for (int b = 0; b < nb; b++) { int t = g_bsums[b]; g_bsums[b] = run; run += t; }
    }
}

__global__ void k_scan3() {
    int i = blockIdx.x * blockDim.x + threadIdx.x;
    if (i == 0) g_offs[0] = 0;
    if (i < NN) g_offs[i + 1] += g_bsums[i >> 10];
}

__global__ void k_scatter(const int* __restrict__ src, const int* __restrict__ dst) {
    int e = blockIdx.x * blockDim.x + threadIdx.x;
    if (e < EE) {
        int d = dst[e];
        int pos = g_offs[d] + atomicAdd(&g_cursor[d], 1);
        g_csr[pos] = src[e];
    }
}

// ===========================================================================
// W-tile prep: [n][k] bf16, hi/lo, padded stride 136 elements.
// ids: 0..16383 -> W0, 16384..32767 -> W1, 32768..40959 -> W2 (n padded to 64)
// ===========================================================================
__global__ void k_wtiles(const float* __restrict__ W0,
                         const float* __restrict__ W1,
                         const float* __restrict__ W2) {
    int id = blockIdx.x * blockDim.x + threadIdx.x;
    if (id >= 40960) return;
    float val;
    unsigned char *ph, *pl;
    int n, k;
    if (id < 32768) {
        const float* W = (id < 16384) ? W0 : W1;
        ph = (id < 16384) ? g_B0h : g_B1h;
        pl = (id < 16384) ? g_B0l : g_B1l;
        int e = id & 16383;
        n = e >> 7; k = e & 127;
        val = W[k * 128 + n];
    } else {
        int e = id - 32768;
        n = e >> 7; k = e & 127;      // n in [0,64)
        val = (n < CD) ? W2[k * CD + n] : 0.f;
        ph = g_B2h; pl = g_B2l;
    }
    __nv_bfloat16 hi = __float2bfloat16(val);
    __nv_bfloat16 lo = __float2bfloat16(val - __bfloat162float(hi));
    uint32_t off = ((uint32_t)n * 136u + (uint32_t)k) * 2u;
    *(__nv_bfloat16*)(ph + off) = hi;
    *(__nv_bfloat16*)(pl + off) = lo;
}

// ===========================================================================
// HMMA GEMM: out[r, 0:OUTC] = norm_out[r] * (x[r, 0:128] @ W)
// CTA: 128 rows x NTILE cols. 8 warps, warp tile 32(m) x NTILE/2(n).
// 3-term bf16 emulation: D = Ah*Bh + Al*Bh + Ah*Bl (fp32 accumulate).
// SMEM: Xh, Xl [128][136]bf16 ; Wh, Wl [NTILE][136]bf16  (dynamic)
// ===========================================================================
template <int NTILE, int OUTC>
__global__ void __launch_bounds__(256)
gemm_mma(const float* __restrict__ xin,
         const unsigned char* __restrict__ Wh,
         const unsigned char* __restrict__ Wl,
         float* __restrict__ out) {
    extern __shared__ __align__(16) unsigned char sm[];
    constexpr int XS    = 136;                    // padded row stride (elems)
    constexpr int XH_OFF = 0;
    constexpr int XL_OFF = 128 * XS * 2;          // 34816
    constexpr int WH_OFF = XL_OFF * 2;            // 69632
    constexpr int WBYTES = NTILE * XS * 2;
    constexpr int WL_OFF = WH_OFF + WBYTES;
    constexpr int NFRAG  = NTILE / 16;            // n8-frags per warp (8 or 4)
    constexpr int NF2    = NFRAG / 2;             // ldmatrix.x4 count (4 or 2)

    const int tid  = threadIdx.x;
    const int wid  = tid >> 5;
    const int lane = tid & 31;
    const int row0 = blockIdx.x * 128;

    // ---- X: load fp32, split bf16 hi/lo, store to smem (conflict-free) ----
    {
        int r  = tid & 127;
        int kh = (tid >> 7) * 64;
        int gr = row0 + r;
        bool ok = gr < NN;
        const float4* xr = (const float4*)&xin[(size_t)gr * 128 + kh];
        uint32_t* xh32 = (uint32_t*)(sm + XH_OFF);
        uint32_t* xl32 = (uint32_t*)(sm + XL_OFF);
        int base32 = (r * XS + kh) >> 1;
        #pragma unroll
        for (int i = 0; i < 8; i++) {         // 8 x (2 float4) = 64 floats
            float4 v0 = ok ? xr[i * 2]     : make_float4(0.f, 0.f, 0.f, 0.f);
            float4 v1 = ok ? xr[i * 2 + 1] : make_float4(0.f, 0.f, 0.f, 0.f);
            __nv_bfloat16 h0 = __float2bfloat16(v0.x), h1 = __float2bfloat16(v0.y);
            __nv_bfloat16 h2 = __float2bfloat16(v0.z), h3 = __float2bfloat16(v0.w);
            __nv_bfloat16 h4 = __float2bfloat16(v1.x), h5 = __float2bfloat16(v1.y);
            __nv_bfloat16 h6 = __float2bfloat16(v1.z), h7 = __float2bfloat16(v1.w);
            __nv_bfloat162 hp0(h0, h1), hp1(h2, h3), hp2(h4, h5), hp3(h6, h7);
            __nv_bfloat162 lp0(__float2bfloat16(v0.x - __bfloat162float(h0)),
                               __float2bfloat16(v0.y - __bfloat162float(h1)));
            __nv_bfloat162 lp1(__float2bfloat16(v0.z - __bfloat162float(h2)),
                               __float2bfloat16(v0.w - __bfloat162float(h3)));
            __nv_bfloat162 lp2(__float2bfloat16(v1.x - __bfloat162float(h4)),
                               __float2bfloat16(v1.y - __bfloat162float(h5)));
            __nv_bfloat162 lp3(__float2bfloat16(v1.z - __bfloat162float(h6)),
                               __float2bfloat16(v1.w - __bfloat162float(h7)));
            uint4 hv = make_uint4(*(uint32_t*)&hp0, *(uint32_t*)&hp1,
                                  *(uint32_t*)&hp2, *(uint32_t*)&hp3);
            uint4 lv = make_uint4(*(uint32_t*)&lp0, *(uint32_t*)&lp1,
                                  *(uint32_t*)&lp2, *(uint32_t*)&lp3);
            *(uint4*)&xh32[base32 + i * 4] = hv;
            *(uint4*)&xl32[base32 + i * 4] = lv;
        }
    }
    // ---- W: verbatim copy (prepped layout == smem layout) ----
    {
        const float4* s4h = (const float4*)Wh;
        const float4* s4l = (const float4*)Wl;
        float4* d4h = (float4*)(sm + WH_OFF);
        float4* d4l = (float4*)(sm + WL_OFF);
        #pragma unroll
        for (int i = tid; i < WBYTES / 16; i += 256) {
            d4h[i] = s4h[i];
            d4l[i] = s4l[i];
        }
    }
    __syncthreads();

    // ---- per-lane ldmatrix base addresses ----
    const int m0 = (wid & 3) * 32;
    const int n0 = (wid >> 2) * (NTILE / 2);
    const uint32_t smb = smem_to_u32(sm);
    uint32_t aH = smb + XH_OFF +
        (uint32_t)(((m0 + (lane & 15)) * XS + (lane >> 4) * 8) * 2);
    uint32_t aL = aH + (XL_OFF - XH_OFF);
    uint32_t bH = smb + WH_OFF +
        (uint32_t)(((n0 + (lane >> 4) * 8 + (lane & 7)) * XS + ((lane >> 3) & 1) * 8) * 2);
    uint32_t bL = bH + WBYTES;

    float acc[2][NFRAG][4];
    #pragma unroll
    for (int mi = 0; mi < 2; mi++)
        #pragma unroll
        for (int f = 0; f < NFRAG; f++)
            #pragma unroll
            for (int q = 0; q < 4; q++) acc[mi][f][q] = 0.f;

    // ---- mainloop: 8 k-steps of 16 ----
    #pragma unroll
    for (int ks = 0; ks < 8; ks++) {
        uint32_t AH[2][4], AL[2][4];
        LDSM4(AH[0], aH);
        LDSM4(AH[1], aH + 16 * XS * 2);
        LDSM4(AL[0], aL);
        LDSM4(AL[1], aL + 16 * XS * 2);
        uint32_t BH[NF2][4], BL[NF2][4];
        #pragma unroll
        for (int j = 0; j < NF2; j++) {
            LDSM4(BH[j], bH + j * 16 * XS * 2);
            LDSM4(BL[j], bL + j * 16 * XS * 2);
        }
        #pragma unroll
        for (int mi = 0; mi < 2; mi++)
            #pragma unroll
            for (int j = 0; j < NF2; j++)
                #pragma unroll
                for (int h = 0; h < 2; h++) {
                    float* c = acc[mi][j * 2 + h];
                    MMA_BF16(c, AH[mi], BH[j][h * 2], BH[j][h * 2 + 1]);
                    MMA_BF16(c, AL[mi], BH[j][h * 2], BH[j][h * 2 + 1]);
                    MMA_BF16(c, AH[mi], BL[j][h * 2], BL[j][h * 2 + 1]);
                }
        aH += 32; aL += 32; bH += 32; bL += 32;   // advance k by 16 elems
    }

    // ---- epilogue: scale by norm_out, store fp32 ----
    const int g  = lane >> 2;
    const int tq = lane & 3;
    #pragma unroll
    for (int mi = 0; mi < 2; mi++) {
        int r1 = row0 + m0 + mi * 16 + g;
        int r2 = r1 + 8;
        float s1 = (r1 < NN) ? g_norm_out[r1] : 0.f;
        float s2 = (r2 < NN) ? g_norm_out[r2] : 0.f;
        #pragma unroll
        for (int f = 0; f < NFRAG; f++) {
            int n = n0 + f * 8 + tq * 2;
            if (OUTC < NTILE && n >= OUTC) continue;
            float* c = acc[mi][f];
            if (r1 < NN)
                *(float2*)&out[(size_t)r1 * OUTC + n] = make_float2(c[0] * s1, c[1] * s1);
            if (r2 < NN)
                *(float2*)&out[(size_t)r2 * OUTC + n] = make_float2(c[2] * s2, c[3] * s2);
        }
    }
}

// ===========================================================================
// Aggregation 128-dim: one warp per dst node; CSR gather-accumulate.
// ===========================================================================
template <int RELU>
__global__ void __launch_bounds__(256)
agg128(const float* __restrict__ bias) {
    int w = (blockIdx.x * blockDim.x + threadIdx.x) >> 5;
    if (w >= NN) return;
    int lane = threadIdx.x & 31;
    int beg = g_offs[w], end = g_offs[w + 1];

    float4 acc = make_float4(0.f, 0.f, 0.f, 0.f);
    int e = beg;
    for (; e + 2 <= end; e += 2) {
        int s0 = g_csr[e];
        int s1 = g_csr[e + 1];
        float4 v0 = *(const float4*)&g_bufA[(size_t)s0 * 128 + lane * 4];
        float4 v1 = *(const float4*)&g_bufA[(size_t)s1 * 128 + lane * 4];
        acc.x += v0.x; acc.y += v0.y; acc.z += v0.z; acc.w += v0.w;
        acc.x += v1.x; acc.y += v1.y; acc.z += v1.z; acc.w += v1.w;
    }
    if (e < end) {
        int s0 = g_csr[e];
        float4 v0 = *(const float4*)&g_bufA[(size_t)s0 * 128 + lane * 4];
        acc.x += v0.x; acc.y += v0.y; acc.z += v0.z; acc.w += v0.w;
    }

    float sc = g_norm_in[w];
    float4 b = *(const float4*)&bias[lane * 4];
    float4 o;
    o.x = fmaf(acc.x, sc, b.x);
    o.y = fmaf(acc.y, sc, b.y);
    o.z = fmaf(acc.z, sc, b.z);
    o.w = fmaf(acc.w, sc, b.w);
    if (RELU) {
        o.x = fmaxf(o.x, 0.f); o.y = fmaxf(o.y, 0.f);
        o.z = fmaxf(o.z, 0.f); o.w = fmaxf(o.w, 0.f);
    }
    *(float4*)&g_bufB[(size_t)w * 128 + lane * 4] = o;
}

// ===========================================================================
// Aggregation 40-dim (final layer, no relu) -> d_out
// ===========================================================================
__global__ void __launch_bounds__(256)
agg40(const float* __restrict__ bias, float* __restrict__ out) {
    int w = (blockIdx.x * blockDim.x + threadIdx.x) >> 5;
    if (w >= NN) return;
    int lane = threadIdx.x & 31;
    int beg = g_offs[w], end = g_offs[w + 1];

    float acc0 = 0.f, acc1 = 0.f;
    for (int e = beg; e < end; e++) {
        int s = g_csr[e];
        const float* rp = &g_bufA[(size_t)s * 40];
        acc0 += rp[lane];
        if (lane < 8) acc1 += rp[32 + lane];
    }
    float sc = g_norm_in[w];
    out[(size_t)w * 40 + lane] = fmaf(acc0, sc, bias[lane]);
    if (lane < 8)
        out[(size_t)w * 40 + 32 + lane] = fmaf(acc1, sc, bias[32 + lane]);
}

// ===========================================================================
extern "C" void kernel_launch(void* const* d_in, const int* in_sizes, int n_in,
                              void* d_out, int out_size) {
    const float* feat = (const float*)d_in[0];
    const int*   src  = (const int*)  d_in[1];
    const int*   dst  = (const int*)  d_in[2];
    const float* W0   = (const float*)d_in[3];
    const float* b0   = (const float*)d_in[4];
    const float* W1   = (const float*)d_in[5];
    const float* b1   = (const float*)d_in[6];
    const float* W2   = (const float*)d_in[7];
    const float* b2   = (const float*)d_in[8];
    float* out = (float*)d_out;

    const int NB = (NN + 255) / 256;
    const int EB = (EE + 255) / 256;
    const int SB = (NN + 1023) / 1024;
    const int AGGB = (NN * 32 + 255) / 256;
    const int GB = (NN + 127) / 128;

    const int SMEM_BIG   = 2 * 128 * 136 * 2 + 2 * 128 * 136 * 2;  // 139264
    const int SMEM_SMALL = 2 * 128 * 136 * 2 + 2 * 64 * 136 * 2;   // 104448
    static bool attr_done = false;
    if (!attr_done) {
        cudaFuncSetAttribute(gemm_mma<128, 128>,
                             cudaFuncAttributeMaxDynamicSharedMemorySize, SMEM_BIG);
        cudaFuncSetAttribute(gemm_mma<64, 40>,
                             cudaFuncAttributeMaxDynamicSharedMemorySize, SMEM_SMALL);
        attr_done = true;
    }

    unsigned char *p_B0h, *p_B0l, *p_B1h, *p_B1l, *p_B2h, *p_B2l;
    cudaGetSymbolAddress((void**)&p_B0h, g_B0h);
    cudaGetSymbolAddress((void**)&p_B0l, g_B0l);
    cudaGetSymbolAddress((void**)&p_B1h, g_B1h);
    cudaGetSymbolAddress((void**)&p_B1l, g_B1l);
    cudaGetSymbolAddress((void**)&p_B2h, g_B2h);
    cudaGetSymbolAddress((void**)&p_B2l, g_B2l);
    float* p_bufA;
    float* p_bufB;
    cudaGetSymbolAddress((void**)&p_bufA, g_bufA);
    cudaGetSymbolAddress((void**)&p_bufB, g_bufB);

    // graph preprocessing + W prep
    k_zero<<<NB, 256>>>();
    k_deg<<<EB, 256>>>(src, dst);
    k_norm<<<NB, 256>>>();
    k_scan1<<<SB, 1024>>>();
    k_scan2<<<1, 32>>>(SB);
    k_scan3<<<NB, 256>>>();
    k_scatter<<<EB, 256>>>(src, dst);
    k_wtiles<<<(40960 + 255) / 256, 256>>>(W0, W1, W2);

    // layer 0
    gemm_mma<128, 128><<<GB, 256, SMEM_BIG>>>(feat, p_B0h, p_B0l, p_bufA);
    agg128<1><<<AGGB, 256>>>(b0);
    // layer 1
    gemm_mma<128, 128><<<GB, 256, SMEM_BIG>>>(p_bufB, p_B1h, p_B1l, p_bufA);
    agg128<1><<<AGGB, 256>>>(b1);
    // layer 2
    gemm_mma<64, 40><<<GB, 256, SMEM_SMALL>>>(p_bufB, p_B2h, p_B2l, p_bufA);
    agg40<<<AGGB, 256>>>(b2, out);
}

// round 5
// speedup vs baseline: 1.4432x; 1.1261x over previous
#include <cuda_runtime.h>
#include <cuda_bf16.h>
#include <cuda_fp16.h>
#include <math.h>
#include <stdint.h>

#define NN 100000
#define EE 1600000
#define HD 128
#define CD 40

// -------- scratch (static __device__ arrays; allocation forbidden) --------
__device__ __half g_hbuf[(size_t)NN * HD];  // 25.6 MB : GEMM out (gather src)
__device__ float  g_bufB[(size_t)NN * HD];  // 51.2 MB : agg out (GEMM in)
__device__ int    g_deg_out[NN];
__device__ int    g_deg_in[NN];
__device__ float  g_norm_out[NN];
__device__ float  g_norm_in[NN];
__device__ int    g_offs[NN + 1];
__device__ int    g_cursor[NN];
__device__ int    g_bsums[128];
__device__ int    g_csr[EE];                // 6.4 MB

// Pre-built W operand tiles: [n][k] bf16, padded row stride 136 elems, hi/lo.
__device__ __align__(16) unsigned char g_B0h[128 * 136 * 2];
__device__ __align__(16) unsigned char g_B0l[128 * 136 * 2];
__device__ __align__(16) unsigned char g_B1h[128 * 136 * 2];
__device__ __align__(16) unsigned char g_B1l[128 * 136 * 2];
__device__ __align__(16) unsigned char g_B2h[64 * 136 * 2];
__device__ __align__(16) unsigned char g_B2l[64 * 136 * 2];

// ===========================================================================
// MMA / ldmatrix helpers (baseline sm_80 features -- no 'a'-gated PTX)
// ===========================================================================
__device__ __forceinline__ uint32_t smem_to_u32(const void* p) {
    uint32_t a;
    asm("{ .reg .u64 t; cvta.to.shared.u64 t, %1; cvt.u32.u64 %0, t; }"
        : "=r"(a) : "l"(p));
    return a;
}

#define LDSM4(r, addr) \
    asm volatile("ldmatrix.sync.aligned.m8n8.x4.shared.b16 {%0,%1,%2,%3}, [%4];" \
        : "=r"((r)[0]), "=r"((r)[1]), "=r"((r)[2]), "=r"((r)[3]) : "r"(addr))

#define MMA_BF16(d, a, b0, b1) \
    asm volatile("mma.sync.aligned.m16n8k16.row.col.f32.bf16.bf16.f32 " \
        "{%0,%1,%2,%3}, {%4,%5,%6,%7}, {%8,%9}, {%0,%1,%2,%3};" \
        : "+f"((d)[0]), "+f"((d)[1]), "+f"((d)[2]), "+f"((d)[3]) \
        : "r"((a)[0]), "r"((a)[1]), "r"((a)[2]), "r"((a)[3]), "r"(b0), "r"(b1))

// ===========================================================================
// Degrees + norms + CSR build
// ===========================================================================
__global__ void k_zero() {
    int i = blockIdx.x * blockDim.x + threadIdx.x;
    if (i < NN) { g_deg_out[i] = 0; g_deg_in[i] = 0; g_cursor[i] = 0; }
}

__global__ void k_deg(const int* __restrict__ src, const int* __restrict__ dst) {
    int e = blockIdx.x * blockDim.x + threadIdx.x;
    if (e < EE) {
        atomicAdd(&g_deg_out[src[e]], 1);
        atomicAdd(&g_deg_in[dst[e]], 1);
    }
}

__global__ void k_norm() {
    int i = blockIdx.x * blockDim.x + threadIdx.x;
    if (i < NN) {
        int d0 = g_deg_out[i];
        int d1 = g_deg_in[i];
        g_norm_out[i] = d0 > 0 ? rsqrtf((float)d0) : 0.f;
        g_norm_in[i]  = d1 > 0 ? rsqrtf((float)d1) : 0.f;
    }
}

__global__ void k_scan1() {
    __shared__ int sh[1024];
    int i = blockIdx.x * 1024 + threadIdx.x;
    int v = (i < NN) ? g_deg_in[i] : 0;
    sh[threadIdx.x] = v;
    __syncthreads();
    #pragma unroll
    for (int d = 1; d < 1024; d <<= 1) {
        int t = 0;
        if ((int)threadIdx.x >= d) t = sh[threadIdx.x - d];
        __syncthreads();
        sh[threadIdx.x] += t;
        __syncthreads();
    }
    if (i < NN) g_offs[i + 1] = sh[threadIdx.x];
    if (threadIdx.x == 1023) g_bsums[blockIdx.x] = sh[1023];
}

__global__ void k_scan2(int nb) {
    if (threadIdx.x == 0 && blockIdx.x == 0) {
        int run = 0;
        for (int b = 0; b < nb; b++) { int t = g_bsums[b]; g_bsums[b] = run; run += t; }
    }
}

__global__ void k_scan3() {
    int i = blockIdx.x * blockDim.x + threadIdx.x;
    if (i == 0) g_offs[0] = 0;
    if (i < NN) g_offs[i + 1] += g_bsums[i >> 10];
}

__global__ void k_scatter(const int* __restrict__ src, const int* __restrict__ dst) {
    int e = blockIdx.x * blockDim.x + threadIdx.x;
    if (e < EE) {
        int d = dst[e];
        int pos = g_offs[d] + atomicAdd(&g_cursor[d], 1);
        g_csr[pos] = src[e];
    }
}

// ===========================================================================
// W-tile prep: [n][k] bf16, hi/lo, padded stride 136 elements.
// ===========================================================================
__global__ void k_wtiles(const float* __restrict__ W0,
                         const float* __restrict__ W1,
                         const float* __restrict__ W2) {
    int id = blockIdx.x * blockDim.x + threadIdx.x;
    if (id >= 40960) return;
    float val;
    unsigned char *ph, *pl;
    int n, k;
    if (id < 32768) {
        const float* W = (id < 16384) ? W0 : W1;
        ph = (id < 16384) ? g_B0h : g_B1h;
        pl = (id < 16384) ? g_B0l : g_B1l;
        int e = id & 16383;
        n = e >> 7; k = e & 127;
        val = W[k * 128 + n];
    } else {
        int e = id - 32768;
        n = e >> 7; k = e & 127;      // n in [0,64)
        val = (n < CD) ? W2[k * CD + n] : 0.f;
        ph = g_B2h; pl = g_B2l;
    }
    __nv_bfloat16 hi = __float2bfloat16(val);
    __nv_bfloat16 lo = __float2bfloat16(val - __bfloat162float(hi));
    uint32_t off = ((uint32_t)n * 136u + (uint32_t)k) * 2u;
    *(__nv_bfloat16*)(ph + off) = hi;
    *(__nv_bfloat16*)(pl + off) = lo;
}

// ===========================================================================
// HMMA GEMM: hout[r, 0:OUTC] = fp16( norm_out[r] * (x[r, 0:128] @ W) )
// CTA: 128 rows x NTILE cols. 8 warps. 3-term bf16 emulation, fp32 accum.
// ===========================================================================
template <int NTILE, int OUTC>
__global__ void __launch_bounds__(256)
gemm_mma(const float* __restrict__ xin,
         const unsigned char* __restrict__ Wh,
         const unsigned char* __restrict__ Wl,
         __half* __restrict__ hout) {
    extern __shared__ __align__(16) unsigned char sm[];
    constexpr int XS    = 136;
    constexpr int XH_OFF = 0;
    constexpr int XL_OFF = 128 * XS * 2;
    constexpr int WH_OFF = XL_OFF * 2;
    constexpr int WBYTES = NTILE * XS * 2;
    constexpr int WL_OFF = WH_OFF + WBYTES;
    constexpr int NFRAG  = NTILE / 16;
    constexpr int NF2    = NFRAG / 2;

    const int tid  = threadIdx.x;
    const int wid  = tid >> 5;
    const int lane = tid & 31;
    const int row0 = blockIdx.x * 128;

    // ---- X: load fp32, split bf16 hi/lo, store to smem ----
    {
        int r  = tid & 127;
        int kh = (tid >> 7) * 64;
        int gr = row0 + r;
        bool ok = gr < NN;
        const float4* xr = (const float4*)&xin[(size_t)gr * 128 + kh];
        uint32_t* xh32 = (uint32_t*)(sm + XH_OFF);
        uint32_t* xl32 = (uint32_t*)(sm + XL_OFF);
        int base32 = (r * XS + kh) >> 1;
        #pragma unroll
        for (int i = 0; i < 8; i++) {
            float4 v0 = ok ? xr[i * 2]     : make_float4(0.f, 0.f, 0.f, 0.f);
            float4 v1 = ok ? xr[i * 2 + 1] : make_float4(0.f, 0.f, 0.f, 0.f);
            __nv_bfloat16 h0 = __float2bfloat16(v0.x), h1 = __float2bfloat16(v0.y);
            __nv_bfloat16 h2 = __float2bfloat16(v0.z), h3 = __float2bfloat16(v0.w);
            __nv_bfloat16 h4 = __float2bfloat16(v1.x), h5 = __float2bfloat16(v1.y);
            __nv_bfloat16 h6 = __float2bfloat16(v1.z), h7 = __float2bfloat16(v1.w);
            __nv_bfloat162 hp0(h0, h1), hp1(h2, h3), hp2(h4, h5), hp3(h6, h7);
            __nv_bfloat162 lp0(__float2bfloat16(v0.x - __bfloat162float(h0)),
                               __float2bfloat16(v0.y - __bfloat162float(h1)));
            __nv_bfloat162 lp1(__float2bfloat16(v0.z - __bfloat162float(h2)),
                               __float2bfloat16(v0.w - __bfloat162float(h3)));
            __nv_bfloat162 lp2(__float2bfloat16(v1.x - __bfloat162float(h4)),
                               __float2bfloat16(v1.y - __bfloat162float(h5)));
            __nv_bfloat162 lp3(__float2bfloat16(v1.z - __bfloat162float(h6)),
                               __float2bfloat16(v1.w - __bfloat162float(h7)));
            uint4 hv = make_uint4(*(uint32_t*)&hp0, *(uint32_t*)&hp1,
                                  *(uint32_t*)&hp2, *(uint32_t*)&hp3);
            uint4 lv = make_uint4(*(uint32_t*)&lp0, *(uint32_t*)&lp1,
                                  *(uint32_t*)&lp2, *(uint32_t*)&lp3);
            *(uint4*)&xh32[base32 + i * 4] = hv;
            *(uint4*)&xl32[base32 + i * 4] = lv;
        }
    }
    // ---- W: verbatim copy ----
    {
        const float4* s4h = (const float4*)Wh;
        const float4* s4l = (const float4*)Wl;
        float4* d4h = (float4*)(sm + WH_OFF);
        float4* d4l = (float4*)(sm + WL_OFF);
        #pragma unroll
        for (int i = tid; i < WBYTES / 16; i += 256) {
            d4h[i] = s4h[i];
            d4l[i] = s4l[i];
        }
    }
    __syncthreads();

    const int m0 = (wid & 3) * 32;
    const int n0 = (wid >> 2) * (NTILE / 2);
    const uint32_t smb = smem_to_u32(sm);
    uint32_t aH = smb + XH_OFF +
        (uint32_t)(((m0 + (lane & 15)) * XS + (lane >> 4) * 8) * 2);
    uint32_t aL = aH + (XL_OFF - XH_OFF);
    uint32_t bH = smb + WH_OFF +
        (uint32_t)(((n0 + (lane >> 4) * 8 + (lane & 7)) * XS + ((lane >> 3) & 1) * 8) * 2);
    uint32_t bL = bH + WBYTES;

    float acc[2][NFRAG][4];
    #pragma unroll
    for (int mi = 0; mi < 2; mi++)
        #pragma unroll
        for (int f = 0; f < NFRAG; f++)
            #pragma unroll
            for (int q = 0; q < 4; q++) acc[mi][f][q] = 0.f;

    #pragma unroll
    for (int ks = 0; ks < 8; ks++) {
        uint32_t AH[2][4], AL[2][4];
        LDSM4(AH[0], aH);
        LDSM4(AH[1], aH + 16 * XS * 2);
        LDSM4(AL[0], aL);
        LDSM4(AL[1], aL + 16 * XS * 2);
        uint32_t BH[NF2][4], BL[NF2][4];
        #pragma unroll
        for (int j = 0; j < NF2; j++) {
            LDSM4(BH[j], bH + j * 16 * XS * 2);
            LDSM4(BL[j], bL + j * 16 * XS * 2);
        }
        #pragma unroll
        for (int mi = 0; mi < 2; mi++)
            #pragma unroll
            for (int j = 0; j < NF2; j++)
                #pragma unroll
                for (int h = 0; h < 2; h++) {
                    float* c = acc[mi][j * 2 + h];
                    MMA_BF16(c, AH[mi], BH[j][h * 2], BH[j][h * 2 + 1]);
                    MMA_BF16(c, AL[mi], BH[j][h * 2], BH[j][h * 2 + 1]);
                    MMA_BF16(c, AH[mi], BL[j][h * 2], BL[j][h * 2 + 1]);
                }
        aH += 32; aL += 32; bH += 32; bL += 32;
    }

    // ---- epilogue: scale by norm_out, store fp16 ----
    const int g  = lane >> 2;
    const int tq = lane & 3;
    #pragma unroll
    for (int mi = 0; mi < 2; mi++) {
        int r1 = row0 + m0 + mi * 16 + g;
        int r2 = r1 + 8;
        float s1 = (r1 < NN) ? g_norm_out[r1] : 0.f;
        float s2 = (r2 < NN) ? g_norm_out[r2] : 0.f;
        #pragma unroll
        for (int f = 0; f < NFRAG; f++) {
            int n = n0 + f * 8 + tq * 2;
            if (OUTC < NTILE && n >= OUTC) continue;
            float* c = acc[mi][f];
            if (r1 < NN) {
                __half2 hv = __floats2half2_rn(c[0] * s1, c[1] * s1);
                *(__half2*)&hout[(size_t)r1 * OUTC + n] = hv;
            }
            if (r2 < NN) {
                __half2 hv = __floats2half2_rn(c[2] * s2, c[3] * s2);
                *(__half2*)&hout[(size_t)r2 * OUTC + n] = hv;
            }
        }
    }
}

// ===========================================================================
// Aggregation 128-dim: one warp per dst node; CSR gather (fp16), fp32 accum.
// g_bufB[w,:] = relu( (sum g_hbuf[src_e,:]) * norm_in[w] + bias )
// ===========================================================================
template <int RELU>
__global__ void __launch_bounds__(256)
agg128(const float* __restrict__ bias) {
    int w = (blockIdx.x * blockDim.x + threadIdx.x) >> 5;
    if (w >= NN) return;
    int lane = threadIdx.x & 31;
    int beg = g_offs[w], end = g_offs[w + 1];

    float4 acc = make_float4(0.f, 0.f, 0.f, 0.f);
    int e = beg;
    for (; e + 4 <= end; e += 4) {
        int s0 = g_csr[e],     s1 = g_csr[e + 1];
        int s2 = g_csr[e + 2], s3 = g_csr[e + 3];
        uint2 u0 = *(const uint2*)&g_hbuf[(size_t)s0 * 128 + lane * 4];
        uint2 u1 = *(const uint2*)&g_hbuf[(size_t)s1 * 128 + lane * 4];
        uint2 u2 = *(const uint2*)&g_hbuf[(size_t)s2 * 128 + lane * 4];
        uint2 u3 = *(const uint2*)&g_hbuf[(size_t)s3 * 128 + lane * 4];
        float2 a0 = __half22float2(*(__half2*)&u0.x), b0 = __half22float2(*(__half2*)&u0.y);
        float2 a1 = __half22float2(*(__half2*)&u1.x), b1 = __half22float2(*(__half2*)&u1.y);
        float2 a2 = __half22float2(*(__half2*)&u2.x), b2 = __half22float2(*(__half2*)&u2.y);
        float2 a3 = __half22float2(*(__half2*)&u3.x), b3 = __half22float2(*(__half2*)&u3.y);
        acc.x += (a0.x + a1.x) + (a2.x + a3.x);
        acc.y += (a0.y + a1.y) + (a2.y + a3.y);
        acc.z += (b0.x + b1.x) + (b2.x + b3.x);
        acc.w += (b0.y + b1.y) + (b2.y + b3.y);
    }
    for (; e < end; e++) {
        int s0 = g_csr[e];
        uint2 u0 = *(const uint2*)&g_hbuf[(size_t)s0 * 128 + lane * 4];
        float2 a0 = __half22float2(*(__half2*)&u0.x), b0 = __half22float2(*(__half2*)&u0.y);
        acc.x += a0.x; acc.y += a0.y; acc.z += b0.x; acc.w += b0.y;
    }

    float sc = g_norm_in[w];
    float4 b = *(const float4*)&bias[lane * 4];
    float4 o;
    o.x = fmaf(acc.x, sc, b.x);
    o.y = fmaf(acc.y, sc, b.y);
    o.z = fmaf(acc.z, sc, b.z);
    o.w = fmaf(acc.w, sc, b.w);
    if (RELU) {
        o.x = fmaxf(o.x, 0.f); o.y = fmaxf(o.y, 0.f);
        o.z = fmaxf(o.z, 0.f); o.w = fmaxf(o.w, 0.f);
    }
    *(float4*)&g_bufB[(size_t)w * 128 + lane * 4] = o;
}

// ===========================================================================
// Aggregation 40-dim (final layer, no relu) -> d_out (fp32)
// lane < 20 handles cols [lane*2, lane*2+1]
// ===========================================================================
__global__ void __launch_bounds__(256)
agg40(const float* __restrict__ bias, float* __restrict__ out) {
    int w = (blockIdx.x * blockDim.x + threadIdx.x) >> 5;
    if (w >= NN) return;
    int lane = threadIdx.x & 31;
    int beg = g_offs[w], end = g_offs[w + 1];
    if (lane >= 20) return;

    float2 acc = make_float2(0.f, 0.f);
    int e = beg;
    for (; e + 2 <= end; e += 2) {
        int s0 = g_csr[e], s1 = g_csr[e + 1];
        __half2 h0 = *(const __half2*)&g_hbuf[(size_t)s0 * 40 + lane * 2];
        __half2 h1 = *(const __half2*)&g_hbuf[(size_t)s1 * 40 + lane * 2];
        float2 f0 = __half22float2(h0);
        float2 f1 = __half22float2(h1);
        acc.x += f0.x + f1.x;
        acc.y += f0.y + f1.y;
    }
    if (e < end) {
        int s0 = g_csr[e];
        float2 f0 = __half22float2(*(const __half2*)&g_hbuf[(size_t)s0 * 40 + lane * 2]);
        acc.x += f0.x; acc.y += f0.y;
    }
    float sc = g_norm_in[w];
    float2 o;
    o.x = fmaf(acc.x, sc, bias[lane * 2]);
    o.y = fmaf(acc.y, sc, bias[lane * 2 + 1]);
    *(float2*)&out[(size_t)w * 40 + lane * 2] = o;
}

// ===========================================================================
extern "C" void kernel_launch(void* const* d_in, const int* in_sizes, int n_in,
                              void* d_out, int out_size) {
    const float* feat = (const float*)d_in[0];
    const int*   src  = (const int*)  d_in[1];
    const int*   dst  = (const int*)  d_in[2];
    const float* W0   = (const float*)d_in[3];
    const float* b0   = (const float*)d_in[4];
    const float* W1   = (const float*)d_in[5];
    const float* b1   = (const float*)d_in[6];
    const float* W2   = (const float*)d_in[7];
    const float* b2   = (const float*)d_in[8];
    float* out = (float*)d_out;

    const int NB = (NN + 255) / 256;
    const int EB = (EE + 255) / 256;
    const int SB = (NN + 1023) / 1024;
    const int AGGB = (NN * 32 + 255) / 256;
    const int GB = (NN + 127) / 128;

    const int SMEM_BIG   = 2 * 128 * 136 * 2 + 2 * 128 * 136 * 2;  // 139264
    const int SMEM_SMALL = 2 * 128 * 136 * 2 + 2 * 64 * 136 * 2;   // 104448
    static bool attr_done = false;
    if (!attr_done) {
        cudaFuncSetAttribute(gemm_mma<128, 128>,
                             cudaFuncAttributeMaxDynamicSharedMemorySize, SMEM_BIG);
        cudaFuncSetAttribute(gemm_mma<64, 40>,
                             cudaFuncAttributeMaxDynamicSharedMemorySize, SMEM_SMALL);
        attr_done = true;
    }

    unsigned char *p_B0h, *p_B0l, *p_B1h, *p_B1l, *p_B2h, *p_B2l;
    cudaGetSymbolAddress((void**)&p_B0h, g_B0h);
    cudaGetSymbolAddress((void**)&p_B0l, g_B0l);
    cudaGetSymbolAddress((void**)&p_B1h, g_B1h);
    cudaGetSymbolAddress((void**)&p_B1l, g_B1l);
    cudaGetSymbolAddress((void**)&p_B2h, g_B2h);
    cudaGetSymbolAddress((void**)&p_B2l, g_B2l);
    __half* p_hbuf;
    float*  p_bufB;
    cudaGetSymbolAddress((void**)&p_hbuf, g_hbuf);
    cudaGetSymbolAddress((void**)&p_bufB, g_bufB);

    // graph preprocessing + W prep
    k_zero<<<NB, 256>>>();
    k_deg<<<EB, 256>>>(src, dst);
    k_norm<<<NB, 256>>>();
    k_scan1<<<SB, 1024>>>();
    k_scan2<<<1, 32>>>(SB);
    k_scan3<<<NB, 256>>>();
    k_scatter<<<EB, 256>>>(src, dst);
    k_wtiles<<<(40960 + 255) / 256, 256>>>(W0, W1, W2);

    // layer 0
    gemm_mma<128, 128><<<GB, 256, SMEM_BIG>>>(feat, p_B0h, p_B0l, p_hbuf);
    agg128<1><<<AGGB, 256>>>(b0);
    // layer 1
    gemm_mma<128, 128><<<GB, 256, SMEM_BIG>>>(p_bufB, p_B1h, p_B1l, p_hbuf);
    agg128<1><<<AGGB, 256>>>(b1);
    // layer 2
    gemm_mma<64, 40><<<GB, 256, SMEM_SMALL>>>(p_bufB, p_B2h, p_B2l, p_hbuf);
    agg40<<<AGGB, 256>>>(b2, out);
}